// round 1
// baseline (speedup 1.0000x reference)
#include <cuda_runtime.h>
#include <cuda_bf16.h>

#define N_X     130
#define N_INT   128
#define BATCH   64
#define LATENT  8
#define HIDDEN  64
#define IN_DIM  12
#define STAB    0.1f
#define MAX_ITER 6

__global__ void __launch_bounds__(N_INT, 1)
pde_newton_kernel(const float* __restrict__ u0,
                  const float* __restrict__ zb,
                  const float* __restrict__ x,
                  const float* __restrict__ W1,
                  const float* __restrict__ b1,
                  const float* __restrict__ W2,
                  const float* __restrict__ b2,
                  float* __restrict__ out)
{
    __shared__ float W1s[IN_DIM * HIDDEN];
    __shared__ float b1s[HIDDEN];
    __shared__ float W2s[HIDDEN];
    __shared__ float zs[LATENT];
    __shared__ float xs[N_X];
    __shared__ float us[N_INT + 2];          // zero-padded u
    __shared__ float A[N_INT], B[N_INT], C[N_INT], D[N_INT];
    __shared__ float b2s;

    const int tid = threadIdx.x;
    const int bid = blockIdx.x;

    // ---- cooperative loads ----
    for (int i = tid; i < IN_DIM * HIDDEN; i += N_INT) W1s[i] = W1[i];
    if (tid < HIDDEN) { b1s[tid] = b1[tid]; W2s[tid] = W2[tid]; }
    if (tid < LATENT) zs[tid] = zb[bid * LATENT + tid];
    for (int i = tid; i < N_X; i += N_INT) xs[i] = x[i];
    if (tid == 0) { b2s = b2[0]; us[0] = 0.0f; us[N_INT + 1] = 0.0f; }
    us[tid + 1] = u0[bid * N_INT + tid];
    __syncthreads();

    const int i = tid;                       // interior index; padded index i+1
    const float xi       = xs[i + 1];
    const float inv_dx2  = 1.0f / (xs[i + 2] - xs[i]);            // d(ux)/du[i+1]
    const float hf       = xs[i + 2] - xs[i + 1];
    const float hb       = xs[i + 1] - xs[i];
    const float inv_hfhb = 1.0f / (hf * hb);                      // uxx scale

    // ---- precompute iteration-invariant part of the preactivation ----
    // pre_c[j] = b1[j] + x*W1[0,j] + sum_k z[k]*W1[4+k,j]
    float pre_c[HIDDEN];
    float zreg[LATENT];
#pragma unroll
    for (int k = 0; k < LATENT; k++) zreg[k] = zs[k];
#pragma unroll
    for (int j = 0; j < HIDDEN; j++) {
        float pc = fmaf(xi, W1s[0 * HIDDEN + j], b1s[j]);
#pragma unroll
        for (int k = 0; k < LATENT; k++)
            pc = fmaf(zreg[k], W1s[(4 + k) * HIDDEN + j], pc);
        pre_c[j] = pc;
    }

    for (int iter = 0; iter < MAX_ITER; iter++) {
        const float um = us[i];
        const float uc = us[i + 1];
        const float up = us[i + 2];
        const float ux  = (up - um) * inv_dx2;
        const float uxx = (up - 2.0f * uc + um) * inv_hfhb;

        float acc_res = 0.0f, acc_du = 0.0f, acc_dux = 0.0f, acc_duxx = 0.0f;
#pragma unroll
        for (int j = 0; j < HIDDEN; j++) {
            float pre = pre_c[j];
            pre = fmaf(uc,  W1s[1 * HIDDEN + j], pre);
            pre = fmaf(ux,  W1s[2 * HIDDEN + j], pre);
            pre = fmaf(uxx, W1s[3 * HIDDEN + j], pre);
            const float t  = tanhf(pre);
            const float w2 = W2s[j];
            acc_res = fmaf(t, w2, acc_res);
            const float g = w2 * (1.0f - t * t);
            acc_du   = fmaf(g, W1s[1 * HIDDEN + j], acc_du);
            acc_dux  = fmaf(g, W1s[2 * HIDDEN + j], acc_dux);
            acc_duxx = fmaf(g, W1s[3 * HIDDEN + j], acc_duxx);
        }

        const float r    = acc_res + b2s + STAB * uxx;
        const float q    = (acc_duxx + STAB) * inv_hfhb;
        const float diag = acc_du - 2.0f * q;
        const float sub  = fmaf(-acc_dux, inv_dx2, q);   // dr[i]/du[i-1]
        const float sup  = fmaf( acc_dux, inv_dx2, q);   // dr[i]/du[i+1]

        A[i] = (i == 0)         ? 0.0f : sub;
        B[i] = diag;
        C[i] = (i == N_INT - 1) ? 0.0f : sup;
        D[i] = r;
        __syncthreads();

        // ---- parallel cyclic reduction: 7 steps decouple n=128 ----
#pragma unroll
        for (int s = 1; s < N_INT; s <<= 1) {
            const float am = A[i], bm = B[i], cm = C[i], dm = D[i];
            float a_lo = 0.f, b_lo = 1.f, c_lo = 0.f, d_lo = 0.f;
            float a_hi = 0.f, b_hi = 1.f, c_hi = 0.f, d_hi = 0.f;
            if (i - s >= 0)    { a_lo = A[i - s]; b_lo = B[i - s]; c_lo = C[i - s]; d_lo = D[i - s]; }
            if (i + s < N_INT) { a_hi = A[i + s]; b_hi = B[i + s]; c_hi = C[i + s]; d_hi = D[i + s]; }
            const float alpha = (i - s >= 0)    ? (-am / b_lo) : 0.0f;
            const float beta  = (i + s < N_INT) ? (-cm / b_hi) : 0.0f;
            const float na = alpha * a_lo;
            const float nb = bm + alpha * c_lo + beta * a_hi;
            const float nc = beta * c_hi;
            const float nd = dm + alpha * d_lo + beta * d_hi;
            __syncthreads();
            A[i] = na; B[i] = nb; C[i] = nc; D[i] = nd;
            __syncthreads();
        }

        const float du = D[i] / B[i];
        us[i + 1] = uc - du;                 // DAMP = 1
        __syncthreads();
    }

    out[bid * N_INT + i] = us[i + 1];
}

extern "C" void kernel_launch(void* const* d_in, const int* in_sizes, int n_in,
                              void* d_out, int out_size)
{
    const float* u0 = (const float*)d_in[0];   // u_int_batch [64,128]
    const float* zb = (const float*)d_in[1];   // z_batch     [64,8]
    const float* x  = (const float*)d_in[2];   // x           [130]
    const float* W1 = (const float*)d_in[3];   // [12,64]
    const float* b1 = (const float*)d_in[4];   // [64]
    const float* W2 = (const float*)d_in[5];   // [64,1]
    const float* b2 = (const float*)d_in[6];   // [1]
    pde_newton_kernel<<<BATCH, N_INT>>>(u0, zb, x, W1, b1, W2, b2, (float*)d_out);
}

// round 2
// speedup vs baseline: 1.4716x; 1.4716x over previous
#include <cuda_runtime.h>
#include <math.h>

#define N_X      130
#define N_INT    128
#define BATCH    64
#define LATENT   8
#define HIDDEN   64
#define IN_DIM   12
#define STAB     0.1f
#define MAX_ITER 6
#define GROUPS   4
#define JPT      (HIDDEN / GROUPS)   // 16 hidden units per thread
#define NT       (N_INT * GROUPS)    // 512 threads

__device__ __forceinline__ float tanh_fast(float v) {
    float y;
    asm("tanh.approx.f32 %0, %1;" : "=f"(y) : "f"(v));
    return y;
}

__global__ void __launch_bounds__(NT, 1)
pde_newton_kernel(const float* __restrict__ u0,
                  const float* __restrict__ zb,
                  const float* __restrict__ x,
                  const float* __restrict__ W1,
                  const float* __restrict__ b1,
                  const float* __restrict__ W2,
                  const float* __restrict__ b2,
                  float* __restrict__ out)
{
    __shared__ float  W1s[IN_DIM * HIDDEN];
    __shared__ float  b1s[HIDDEN];
    __shared__ float  W2s[HIDDEN];
    __shared__ float  zs[LATENT];
    __shared__ float  xs[N_X];
    __shared__ float  us[N_INT + 2];          // zero Dirichlet padding
    __shared__ float4 red[NT];                // per-thread partial sums
    __shared__ float  Ab[2][N_INT], Bb[2][N_INT], Cb[2][N_INT], Db[2][N_INT];
    __shared__ float  b2s;

    const int tid = threadIdx.x;
    const int bid = blockIdx.x;
    const int i   = tid & (N_INT - 1);        // interior point
    const int g   = tid >> 7;                 // hidden group 0..3

    // ---- cooperative loads ----
    for (int k = tid; k < IN_DIM * HIDDEN; k += NT) W1s[k] = W1[k];
    if (tid < HIDDEN) { b1s[tid] = b1[tid]; W2s[tid] = W2[tid]; }
    if (tid < LATENT) zs[tid] = zb[bid * LATENT + tid];
    if (tid < N_X)    xs[tid] = x[tid];
    if (tid == 0) { b2s = b2[0]; us[0] = 0.0f; us[N_INT + 1] = 0.0f; }
    if (tid < N_INT) us[tid + 1] = u0[bid * N_INT + tid];
    __syncthreads();

    const float xi       = xs[i + 1];
    const float inv_dx2  = 1.0f / (xs[i + 2] - xs[i]);
    const float inv_hfhb = 1.0f / ((xs[i + 2] - xs[i + 1]) * (xs[i + 1] - xs[i]));

    // ---- iteration-invariant preactivation part for this thread's 16 units ----
    const int j0 = g * JPT;
    float pre_c[JPT];
#pragma unroll
    for (int jj = 0; jj < JPT; jj++) {
        const int j = j0 + jj;
        float pc = fmaf(xi, W1s[j], b1s[j]);
#pragma unroll
        for (int k = 0; k < LATENT; k++)
            pc = fmaf(zs[k], W1s[(4 + k) * HIDDEN + j], pc);
        pre_c[jj] = pc;
    }

#pragma unroll 1
    for (int iter = 0; iter < MAX_ITER; iter++) {
        const bool precise = (iter == MAX_ITER - 1);   // exact residual on last step

        const float um  = us[i];
        const float uc  = us[i + 1];
        const float up  = us[i + 2];
        const float ux  = (up - um) * inv_dx2;
        const float uxx = (up - 2.0f * uc + um) * inv_hfhb;

        // ---- fused MLP forward + analytic tridiagonal Jacobian (partial) ----
        float a0 = 0.f, a1 = 0.f, a2 = 0.f, a3 = 0.f;
#pragma unroll
        for (int jj = 0; jj < JPT; jj++) {
            const int j = j0 + jj;
            // W1s reads are warp-uniform (same g per warp) -> LDS broadcast
            const float w1u  = W1s[1 * HIDDEN + j];
            const float w1x  = W1s[2 * HIDDEN + j];
            const float w1xx = W1s[3 * HIDDEN + j];
            float pre = pre_c[jj];
            pre = fmaf(uc,  w1u,  pre);
            pre = fmaf(ux,  w1x,  pre);
            pre = fmaf(uxx, w1xx, pre);
            const float t  = precise ? tanhf(pre) : tanh_fast(pre);
            const float w2 = W2s[j];
            a0 = fmaf(t, w2, a0);
            const float gg = w2 * (1.0f - t * t);
            a1 = fmaf(gg, w1u,  a1);
            a2 = fmaf(gg, w1x,  a2);
            a3 = fmaf(gg, w1xx, a3);
        }
        red[tid] = make_float4(a0, a1, a2, a3);
        __syncthreads();

        // ---- group-0 reduces across 4 groups and builds tridiagonal system ----
        if (g == 0) {
            const float4 r0 = red[i];
            const float4 r1 = red[i + 128];
            const float4 r2 = red[i + 256];
            const float4 r3 = red[i + 384];
            const float acc_res  = (r0.x + r1.x) + (r2.x + r3.x);
            const float acc_du   = (r0.y + r1.y) + (r2.y + r3.y);
            const float acc_dux  = (r0.z + r1.z) + (r2.z + r3.z);
            const float acc_duxx = (r0.w + r1.w) + (r2.w + r3.w);

            const float r    = acc_res + b2s + STAB * uxx;
            const float q    = (acc_duxx + STAB) * inv_hfhb;
            const float diag = acc_du - 2.0f * q;
            const float sub  = fmaf(-acc_dux, inv_dx2, q);
            const float sup  = fmaf( acc_dux, inv_dx2, q);

            Ab[0][i] = (i == 0)         ? 0.0f : sub;
            Bb[0][i] = diag;
            Cb[0][i] = (i == N_INT - 1) ? 0.0f : sup;
            Db[0][i] = r;
        }
        __syncthreads();

        // ---- parallel cyclic reduction, double buffered: 7 steps, 1 bar each ----
        int p = 0;
#pragma unroll
        for (int s = 1; s < N_INT; s <<= 1) {
            if (g == 0) {
                const float am = Ab[p][i], bm = Bb[p][i], cm = Cb[p][i], dm = Db[p][i];
                float alo = 0.f, blo = 1.f, clo = 0.f, dlo = 0.f;
                float ahi = 0.f, bhi = 1.f, chi = 0.f, dhi = 0.f;
                if (i >= s)         { alo = Ab[p][i - s]; blo = Bb[p][i - s]; clo = Cb[p][i - s]; dlo = Db[p][i - s]; }
                if (i + s < N_INT)  { ahi = Ab[p][i + s]; bhi = Bb[p][i + s]; chi = Cb[p][i + s]; dhi = Db[p][i + s]; }
                const float alpha = (i >= s)        ? -__fdividef(am, blo) : 0.0f;
                const float beta  = (i + s < N_INT) ? -__fdividef(cm, bhi) : 0.0f;
                Ab[p ^ 1][i] = alpha * alo;
                Bb[p ^ 1][i] = fmaf(alpha, clo, fmaf(beta, ahi, bm));
                Cb[p ^ 1][i] = beta * chi;
                Db[p ^ 1][i] = fmaf(alpha, dlo, fmaf(beta, dhi, dm));
            }
            __syncthreads();
            p ^= 1;
        }

        if (g == 0)
            us[i + 1] = uc - __fdividef(Db[p][i], Bb[p][i]);   // DAMP = 1
        __syncthreads();
    }

    if (g == 0)
        out[bid * N_INT + i] = us[i + 1];
}

extern "C" void kernel_launch(void* const* d_in, const int* in_sizes, int n_in,
                              void* d_out, int out_size)
{
    const float* u0 = (const float*)d_in[0];
    const float* zb = (const float*)d_in[1];
    const float* x  = (const float*)d_in[2];
    const float* W1 = (const float*)d_in[3];
    const float* b1 = (const float*)d_in[4];
    const float* W2 = (const float*)d_in[5];
    const float* b2 = (const float*)d_in[6];
    pde_newton_kernel<<<BATCH, NT>>>(u0, zb, x, W1, b1, W2, b2, (float*)d_out);
}